// round 4
// baseline (speedup 1.0000x reference)
#include <cuda_runtime.h>
#include <cstdint>

// Problem constants (fixed by the dataset)
#define NN 30000
#define EE 600000
#define HH 128
#define GG 64
#define LL 4

#define TE 64          // edges (or nodes) per CTA tile
#define AS 260         // smem row stride for A tile (words), keeps float4 alignment
#define KC 16          // k-rows staged per weight chunk

// Scratch (device globals: allocation-free rule). 16B-aligned for float4 ops.
__device__ __align__(16) float g_dist[EE];       // squared distances per edge
__device__ __align__(16) float g_h[NN * HH];     // node features
__device__ __align__(16) float g_aggr[NN * HH];  // scatter-add target
__device__ __align__(16) float g_pool[GG * HH];  // per-graph pooled features

__device__ __forceinline__ float silu_f(float x) {
    return __fdividef(x, 1.0f + __expf(-x));
}

// ---- packed f32x2 helpers (Blackwell dual-FMA pipe; ptxas never auto-fuses) ----
__device__ __forceinline__ uint64_t pack2_dup(float x) {
    uint64_t d; asm("mov.b64 %0, {%1, %1};" : "=l"(d) : "f"(x)); return d;
}
__device__ __forceinline__ void fma2(uint64_t& d, uint64_t a, uint64_t b) {
    asm("fma.rn.f32x2 %0, %1, %2, %0;" : "+l"(d) : "l"(a), "l"(b));
}
__device__ __forceinline__ float2 unpack2(uint64_t d) {
    float2 f; asm("mov.b64 {%0, %1}, %2;" : "=f"(f.x), "=f"(f.y) : "l"(d)); return f;
}

// One k-step: 4 broadcast A values x 8 cols (4 f32x2 pairs) -> 16 FFMA2
__device__ __forceinline__ void step_k(float av0, float av1, float av2, float av3,
                                       const float* sWrow, int tx8,
                                       uint64_t (&acc)[4][4]) {
    uint64_t p0 = pack2_dup(av0), p1 = pack2_dup(av1);
    uint64_t p2 = pack2_dup(av2), p3 = pack2_dup(av3);
    ulonglong2 wA = *(const ulonglong2*)(sWrow + tx8);
    ulonglong2 wB = *(const ulonglong2*)(sWrow + tx8 + 4);
    fma2(acc[0][0], p0, wA.x); fma2(acc[0][1], p0, wA.y);
    fma2(acc[0][2], p0, wB.x); fma2(acc[0][3], p0, wB.y);
    fma2(acc[1][0], p1, wA.x); fma2(acc[1][1], p1, wA.y);
    fma2(acc[1][2], p1, wB.x); fma2(acc[1][3], p1, wB.y);
    fma2(acc[2][0], p2, wA.x); fma2(acc[2][1], p2, wA.y);
    fma2(acc[2][2], p2, wB.x); fma2(acc[2][3], p2, wB.y);
    fma2(acc[3][0], p3, wA.x); fma2(acc[3][1], p3, wA.y);
    fma2(acc[3][2], p3, wB.x); fma2(acc[3][3], p3, wB.y);
}

// ---------------------------------------------------------------------------
__global__ void k_dist(const float* __restrict__ pos, const int* __restrict__ ei) {
    int e = blockIdx.x * blockDim.x + threadIdx.x;
    if (e >= EE) return;
    int r = ei[e];
    int c = ei[EE + e];
    float dx = pos[r * 3 + 0] - pos[c * 3 + 0];
    float dy = pos[r * 3 + 1] - pos[c * 3 + 1];
    float dz = pos[r * 3 + 2] - pos[c * 3 + 2];
    g_dist[e] = dx * dx + dy * dy + dz * dz;
}

__global__ void k_embed(const float* __restrict__ x, const float* __restrict__ w,
                        const float* __restrict__ b) {
    int i = blockIdx.x * blockDim.x + threadIdx.x;
    if (i >= NN * HH) return;
    int n = i >> 7, c = i & 127;
    g_h[i] = x[n] * w[c] + b[c];
}

__global__ void k_zero_aggr() {
    int i = blockIdx.x * blockDim.x + threadIdx.x;
    if (i < NN * HH) g_aggr[i] = 0.0f;
}

__global__ void k_zero_pool() {
    int i = blockIdx.x * blockDim.x + threadIdx.x;
    if (i < GG * HH) g_pool[i] = 0.0f;
}

// ---------------------------------------------------------------------------
// Fused edge message MLP + scatter-add (packed f32x2 math).
// Thread map: tx = tid&15 -> cols tx*8..tx*8+7, ty = tid>>4 -> rows ty+16i.
__global__ __launch_bounds__(256) void k_edge(
    const int* __restrict__ ei,
    const float* __restrict__ w1, const float* __restrict__ b1,
    const float* __restrict__ w2, const float* __restrict__ b2)
{
    extern __shared__ float sm[];
    float* sA = sm;                      // TE * AS floats
    float* sW = sm + TE * AS;            // KC * HH floats
    int* sCol = (int*)(sW + KC * HH);    // TE ints

    const int tid = threadIdx.x;
    const int warp = tid >> 5, lane = tid & 31;
    const int tx8 = (tid & 15) * 8, ty = tid >> 4;
    const int ebase = blockIdx.x * TE;

    // Gather: each warp fills 8 edge rows (coalesced float4 row loads)
    #pragma unroll
    for (int i = 0; i < 8; i++) {
        int el = warp * 8 + i;
        int e = ebase + el;
        int src = ei[e];        // source j
        int dst = ei[EE + e];   // target i
        float4 vi = *(const float4*)(g_h + (size_t)dst * HH + lane * 4);
        float4 vj = *(const float4*)(g_h + (size_t)src * HH + lane * 4);
        *(float4*)(sA + el * AS + lane * 4) = vi;
        *(float4*)(sA + el * AS + 128 + lane * 4) = vj;
        if (lane == 0) { sA[el * AS + 256] = g_dist[e]; sCol[el] = dst; }
    }

    const float* rA0 = sA + (ty     ) * AS;
    const float* rA1 = sA + (ty + 16) * AS;
    const float* rA2 = sA + (ty + 32) * AS;
    const float* rA3 = sA + (ty + 48) * AS;

    uint64_t acc[4][4];
    {   // init with packed bias b1
        ulonglong2 bA = *(const ulonglong2*)(b1 + tx8);
        ulonglong2 bB = *(const ulonglong2*)(b1 + tx8 + 4);
        #pragma unroll
        for (int i = 0; i < 4; i++) {
            acc[i][0] = bA.x; acc[i][1] = bA.y;
            acc[i][2] = bB.x; acc[i][3] = bB.y;
        }
    }

    // GEMM1: K = 256 in chunks of KC, + remainder row 256
    for (int k0 = 0; k0 < 256; k0 += KC) {
        float4 wa = *(const float4*)(w1 + (size_t)k0 * HH + tid * 8);
        float4 wb = *(const float4*)(w1 + (size_t)k0 * HH + tid * 8 + 4);
        __syncthreads();
        *(float4*)(sW + tid * 8) = wa;
        *(float4*)(sW + tid * 8 + 4) = wb;
        __syncthreads();
        #pragma unroll
        for (int kk = 0; kk < KC; kk += 4) {
            float4 a0 = *(const float4*)(rA0 + k0 + kk);
            float4 a1 = *(const float4*)(rA1 + k0 + kk);
            float4 a2 = *(const float4*)(rA2 + k0 + kk);
            float4 a3 = *(const float4*)(rA3 + k0 + kk);
            step_k(a0.x, a1.x, a2.x, a3.x, sW + (kk + 0) * HH, tx8, acc);
            step_k(a0.y, a1.y, a2.y, a3.y, sW + (kk + 1) * HH, tx8, acc);
            step_k(a0.z, a1.z, a2.z, a3.z, sW + (kk + 2) * HH, tx8, acc);
            step_k(a0.w, a1.w, a2.w, a3.w, sW + (kk + 3) * HH, tx8, acc);
        }
    }
    {   // remainder k = 256 (dist column), weights straight from L2
        const float* wr = w1 + (size_t)256 * HH;
        step_k(rA0[256], rA1[256], rA2[256], rA3[256], wr, tx8, acc);
    }
    __syncthreads();

    // silu epilogue -> sA[:, 0:128]; re-init acc with packed bias b2
    #pragma unroll
    for (int i = 0; i < 4; i++) {
        float* dst = sA + (ty + 16 * i) * AS + tx8;
        #pragma unroll
        for (int p = 0; p < 4; p++) {
            float2 v = unpack2(acc[i][p]);
            v.x = silu_f(v.x);
            v.y = silu_f(v.y);
            *(float2*)(dst + 2 * p) = v;
        }
    }
    {
        ulonglong2 bA = *(const ulonglong2*)(b2 + tx8);
        ulonglong2 bB = *(const ulonglong2*)(b2 + tx8 + 4);
        #pragma unroll
        for (int i = 0; i < 4; i++) {
            acc[i][0] = bA.x; acc[i][1] = bA.y;
            acc[i][2] = bB.x; acc[i][3] = bB.y;
        }
    }

    // GEMM2: K = 128
    for (int k0 = 0; k0 < 128; k0 += KC) {
        float4 wa = *(const float4*)(w2 + (size_t)k0 * HH + tid * 8);
        float4 wb = *(const float4*)(w2 + (size_t)k0 * HH + tid * 8 + 4);
        __syncthreads();
        *(float4*)(sW + tid * 8) = wa;
        *(float4*)(sW + tid * 8 + 4) = wb;
        __syncthreads();
        #pragma unroll
        for (int kk = 0; kk < KC; kk += 4) {
            float4 a0 = *(const float4*)(rA0 + k0 + kk);
            float4 a1 = *(const float4*)(rA1 + k0 + kk);
            float4 a2 = *(const float4*)(rA2 + k0 + kk);
            float4 a3 = *(const float4*)(rA3 + k0 + kk);
            step_k(a0.x, a1.x, a2.x, a3.x, sW + (kk + 0) * HH, tx8, acc);
            step_k(a0.y, a1.y, a2.y, a3.y, sW + (kk + 1) * HH, tx8, acc);
            step_k(a0.z, a1.z, a2.z, a3.z, sW + (kk + 2) * HH, tx8, acc);
            step_k(a0.w, a1.w, a2.w, a3.w, sW + (kk + 3) * HH, tx8, acc);
        }
    }

    // scatter-add into aggr[col]
    #pragma unroll
    for (int i = 0; i < 4; i++) {
        float* base = g_aggr + (size_t)sCol[ty + 16 * i] * HH + tx8;
        #pragma unroll
        for (int p = 0; p < 4; p++) {
            float2 v = unpack2(acc[i][p]);
            atomicAdd(base + 2 * p, v.x);
            atomicAdd(base + 2 * p + 1, v.y);
        }
    }
}

// ---------------------------------------------------------------------------
// Fused node-update MLP (packed f32x2). A = [h | aggr] (64 x 256).
__global__ __launch_bounds__(256) void k_node(
    const float* __restrict__ w1, const float* __restrict__ b1,
    const float* __restrict__ w2, const float* __restrict__ b2)
{
    extern __shared__ float sm[];
    float* sA = sm;
    float* sW = sm + TE * AS;

    const int tid = threadIdx.x;
    const int warp = tid >> 5, lane = tid & 31;
    const int tx8 = (tid & 15) * 8, ty = tid >> 4;
    const int nbase = blockIdx.x * TE;

    #pragma unroll
    for (int i = 0; i < 8; i++) {
        int el = warp * 8 + i;
        int n = nbase + el;
        if (n < NN) {
            float4 vh = *(const float4*)(g_h + (size_t)n * HH + lane * 4);
            float4 va = *(const float4*)(g_aggr + (size_t)n * HH + lane * 4);
            *(float4*)(sA + el * AS + lane * 4) = vh;
            *(float4*)(sA + el * AS + 128 + lane * 4) = va;
        } else {
            float4 z = make_float4(0.f, 0.f, 0.f, 0.f);
            *(float4*)(sA + el * AS + lane * 4) = z;
            *(float4*)(sA + el * AS + 128 + lane * 4) = z;
        }
    }

    const float* rA0 = sA + (ty     ) * AS;
    const float* rA1 = sA + (ty + 16) * AS;
    const float* rA2 = sA + (ty + 32) * AS;
    const float* rA3 = sA + (ty + 48) * AS;

    uint64_t acc[4][4];
    {
        ulonglong2 bA = *(const ulonglong2*)(b1 + tx8);
        ulonglong2 bB = *(const ulonglong2*)(b1 + tx8 + 4);
        #pragma unroll
        for (int i = 0; i < 4; i++) {
            acc[i][0] = bA.x; acc[i][1] = bA.y;
            acc[i][2] = bB.x; acc[i][3] = bB.y;
        }
    }

    // GEMM1: K = 256
    for (int k0 = 0; k0 < 256; k0 += KC) {
        float4 wa = *(const float4*)(w1 + (size_t)k0 * HH + tid * 8);
        float4 wb = *(const float4*)(w1 + (size_t)k0 * HH + tid * 8 + 4);
        __syncthreads();
        *(float4*)(sW + tid * 8) = wa;
        *(float4*)(sW + tid * 8 + 4) = wb;
        __syncthreads();
        #pragma unroll
        for (int kk = 0; kk < KC; kk += 4) {
            float4 a0 = *(const float4*)(rA0 + k0 + kk);
            float4 a1 = *(const float4*)(rA1 + k0 + kk);
            float4 a2 = *(const float4*)(rA2 + k0 + kk);
            float4 a3 = *(const float4*)(rA3 + k0 + kk);
            step_k(a0.x, a1.x, a2.x, a3.x, sW + (kk + 0) * HH, tx8, acc);
            step_k(a0.y, a1.y, a2.y, a3.y, sW + (kk + 1) * HH, tx8, acc);
            step_k(a0.z, a1.z, a2.z, a3.z, sW + (kk + 2) * HH, tx8, acc);
            step_k(a0.w, a1.w, a2.w, a3.w, sW + (kk + 3) * HH, tx8, acc);
        }
    }
    __syncthreads();

    #pragma unroll
    for (int i = 0; i < 4; i++) {
        float* dst = sA + (ty + 16 * i) * AS + tx8;
        #pragma unroll
        for (int p = 0; p < 4; p++) {
            float2 v = unpack2(acc[i][p]);
            v.x = silu_f(v.x);
            v.y = silu_f(v.y);
            *(float2*)(dst + 2 * p) = v;
        }
    }
    {
        ulonglong2 bA = *(const ulonglong2*)(b2 + tx8);
        ulonglong2 bB = *(const ulonglong2*)(b2 + tx8 + 4);
        #pragma unroll
        for (int i = 0; i < 4; i++) {
            acc[i][0] = bA.x; acc[i][1] = bA.y;
            acc[i][2] = bB.x; acc[i][3] = bB.y;
        }
    }

    // GEMM2: K = 128
    for (int k0 = 0; k0 < 128; k0 += KC) {
        float4 wa = *(const float4*)(w2 + (size_t)k0 * HH + tid * 8);
        float4 wb = *(const float4*)(w2 + (size_t)k0 * HH + tid * 8 + 4);
        __syncthreads();
        *(float4*)(sW + tid * 8) = wa;
        *(float4*)(sW + tid * 8 + 4) = wb;
        __syncthreads();
        #pragma unroll
        for (int kk = 0; kk < KC; kk += 4) {
            float4 a0 = *(const float4*)(rA0 + k0 + kk);
            float4 a1 = *(const float4*)(rA1 + k0 + kk);
            float4 a2 = *(const float4*)(rA2 + k0 + kk);
            float4 a3 = *(const float4*)(rA3 + k0 + kk);
            step_k(a0.x, a1.x, a2.x, a3.x, sW + (kk + 0) * HH, tx8, acc);
            step_k(a0.y, a1.y, a2.y, a3.y, sW + (kk + 1) * HH, tx8, acc);
            step_k(a0.z, a1.z, a2.z, a3.z, sW + (kk + 2) * HH, tx8, acc);
            step_k(a0.w, a1.w, a2.w, a3.w, sW + (kk + 3) * HH, tx8, acc);
        }
    }

    #pragma unroll
    for (int i = 0; i < 4; i++) {
        int n = nbase + ty + 16 * i;
        if (n < NN) {
            float* dst = g_h + (size_t)n * HH + tx8;
            #pragma unroll
            for (int p = 0; p < 4; p++) {
                float2 v = unpack2(acc[i][p]);
                *(float2*)(dst + 2 * p) = v;
            }
        }
    }
}

// ---------------------------------------------------------------------------
__global__ void k_pool(const int* __restrict__ batch) {
    int i = blockIdx.x * blockDim.x + threadIdx.x;
    if (i >= NN * 32) return;
    int n = i >> 5, c4 = (i & 31) * 4;
    int b = batch[n];
    const float* hr = g_h + (size_t)n * HH + c4;
    float* pr = g_pool + (size_t)b * HH + c4;
    atomicAdd(pr + 0, hr[0]);
    atomicAdd(pr + 1, hr[1]);
    atomicAdd(pr + 2, hr[2]);
    atomicAdd(pr + 3, hr[3]);
}

__global__ void k_out(const float* __restrict__ w1, const float* __restrict__ b1,
                      const float* __restrict__ w2, const float* __restrict__ b2,
                      float* __restrict__ out) {
    __shared__ float sg[GG * HH];   // 32 KB
    __shared__ float sh[GG * 32];   // 8 KB
    int tid = threadIdx.x;
    for (int i = tid; i < GG * HH; i += 256) sg[i] = g_pool[i];
    __syncthreads();
    for (int p = tid; p < GG * 32; p += 256) {
        int g = p >> 5, j = p & 31;
        float s = b1[j];
        #pragma unroll 4
        for (int k = 0; k < HH; k++) s += sg[g * HH + k] * w1[k * 32 + j];
        sh[p] = silu_f(s);
    }
    __syncthreads();
    if (tid < GG) {
        float s = b2[0];
        #pragma unroll
        for (int j = 0; j < 32; j++) s += sh[tid * 32 + j] * w2[j];
        out[tid] = s;
    }
}

// ---------------------------------------------------------------------------
extern "C" void kernel_launch(void* const* d_in, const int* in_sizes, int n_in,
                              void* d_out, int out_size) {
    const float* x       = (const float*)d_in[0];
    const float* pos     = (const float*)d_in[1];
    const int*   ei      = (const int*)d_in[2];
    const int*   batch   = (const int*)d_in[3];
    const float* emb_w   = (const float*)d_in[4];
    const float* emb_b   = (const float*)d_in[5];
    const float* msg_w1  = (const float*)d_in[6];
    const float* msg_b1  = (const float*)d_in[7];
    const float* msg_w2  = (const float*)d_in[8];
    const float* msg_b2  = (const float*)d_in[9];
    const float* node_w1 = (const float*)d_in[10];
    const float* node_b1 = (const float*)d_in[11];
    const float* node_w2 = (const float*)d_in[12];
    const float* node_b2 = (const float*)d_in[13];
    const float* out_w1  = (const float*)d_in[14];
    const float* out_b1  = (const float*)d_in[15];
    const float* out_w2  = (const float*)d_in[16];
    const float* out_b2  = (const float*)d_in[17];
    float* out = (float*)d_out;

    const int SMEM_EDGE = (TE * AS + KC * HH) * 4 + TE * 4;  // 75008 B
    const int SMEM_NODE = (TE * AS + KC * HH) * 4;           // 74752 B
    cudaFuncSetAttribute(k_edge, cudaFuncAttributeMaxDynamicSharedMemorySize, SMEM_EDGE);
    cudaFuncSetAttribute(k_node, cudaFuncAttributeMaxDynamicSharedMemorySize, SMEM_NODE);

    k_dist<<<(EE + 255) / 256, 256>>>(pos, ei);
    k_embed<<<(NN * HH + 255) / 256, 256>>>(x, emb_w, emb_b);

    for (int l = 0; l < LL; l++) {
        k_zero_aggr<<<(NN * HH + 255) / 256, 256>>>();
        k_edge<<<EE / TE, 256, SMEM_EDGE>>>(
            ei,
            msg_w1 + (size_t)l * (2 * HH + 1) * HH, msg_b1 + (size_t)l * HH,
            msg_w2 + (size_t)l * HH * HH,           msg_b2 + (size_t)l * HH);
        k_node<<<(NN + TE - 1) / TE, 256, SMEM_NODE>>>(
            node_w1 + (size_t)l * 2 * HH * HH, node_b1 + (size_t)l * HH,
            node_w2 + (size_t)l * HH * HH,     node_b2 + (size_t)l * HH);
    }

    k_zero_pool<<<(GG * HH + 255) / 256, 256>>>();
    k_pool<<<(NN * 32 + 255) / 256, 256>>>(batch);
    k_out<<<1, 256>>>(out_w1, out_b1, out_w2, out_b2, out);
}

// round 5
// speedup vs baseline: 1.6329x; 1.6329x over previous
#include <cuda_runtime.h>
#include <cstdint>

// Problem constants (fixed by the dataset)
#define NN 30000
#define EE 600000
#define HH 128
#define GG 64
#define LL 4

#define TE 64          // edges (or nodes) per CTA tile
#define AS 260         // smem row stride for A tile (words), keeps float4 alignment
#define KC 16          // k-rows staged per weight chunk

// Scratch (device globals: allocation-free rule). 16B-aligned for float4 ops.
__device__ __align__(16) float g_dist[EE];       // squared distances per edge
__device__ __align__(16) float g_h[NN * HH];     // node features
__device__ __align__(16) float g_aggr[NN * HH];  // scatter-add target
__device__ __align__(16) float g_pool[GG * HH];  // per-graph pooled features

__device__ __forceinline__ float silu_f(float x) {
    return __fdividef(x, 1.0f + __expf(-x));
}

// ---- packed f32x2 helpers ----
__device__ __forceinline__ uint64_t pack2_dup(float x) {
    uint64_t d; asm("mov.b64 %0, {%1, %1};" : "=l"(d) : "f"(x)); return d;
}
__device__ __forceinline__ void fma2(uint64_t& d, uint64_t a, uint64_t b) {
    asm("fma.rn.f32x2 %0, %1, %2, %0;" : "+l"(d) : "l"(a), "l"(b));
}
__device__ __forceinline__ float2 unpack2(uint64_t d) {
    float2 f; asm("mov.b64 {%0, %1}, %2;" : "=f"(f.x), "=f"(f.y) : "l"(d)); return f;
}

// One k-step. Column map: thread owns col pairs {2*tx + 32*p}, p=0..3.
// W fetch = 4 x LDS.64, 8B stride across 16 lanes -> contiguous 128B span,
// conflict-free (upper half-warp broadcasts). 16 FFMA2 per call.
__device__ __forceinline__ void step_k(float av0, float av1, float av2, float av3,
                                       const float* sWrow, int tx2,
                                       uint64_t (&acc)[4][4]) {
    uint64_t p0 = pack2_dup(av0), p1 = pack2_dup(av1);
    uint64_t p2 = pack2_dup(av2), p3 = pack2_dup(av3);
    uint64_t w0 = *(const uint64_t*)(sWrow + tx2);
    uint64_t w1 = *(const uint64_t*)(sWrow + tx2 + 32);
    uint64_t w2 = *(const uint64_t*)(sWrow + tx2 + 64);
    uint64_t w3 = *(const uint64_t*)(sWrow + tx2 + 96);
    fma2(acc[0][0], p0, w0); fma2(acc[0][1], p0, w1);
    fma2(acc[0][2], p0, w2); fma2(acc[0][3], p0, w3);
    fma2(acc[1][0], p1, w0); fma2(acc[1][1], p1, w1);
    fma2(acc[1][2], p1, w2); fma2(acc[1][3], p1, w3);
    fma2(acc[2][0], p2, w0); fma2(acc[2][1], p2, w1);
    fma2(acc[2][2], p2, w2); fma2(acc[2][3], p2, w3);
    fma2(acc[3][0], p3, w0); fma2(acc[3][1], p3, w1);
    fma2(acc[3][2], p3, w2); fma2(acc[3][3], p3, w3);
}

// init accumulators from bias at the pair-interleaved columns
__device__ __forceinline__ void init_acc(const float* b, int tx2, uint64_t (&acc)[4][4]) {
    uint64_t b0 = *(const uint64_t*)(b + tx2);
    uint64_t b1 = *(const uint64_t*)(b + tx2 + 32);
    uint64_t b2 = *(const uint64_t*)(b + tx2 + 64);
    uint64_t b3 = *(const uint64_t*)(b + tx2 + 96);
    #pragma unroll
    for (int i = 0; i < 4; i++) {
        acc[i][0] = b0; acc[i][1] = b1; acc[i][2] = b2; acc[i][3] = b3;
    }
}

// ---------------------------------------------------------------------------
__global__ void k_dist(const float* __restrict__ pos, const int* __restrict__ ei) {
    int e = blockIdx.x * blockDim.x + threadIdx.x;
    if (e >= EE) return;
    int r = ei[e];
    int c = ei[EE + e];
    float dx = pos[r * 3 + 0] - pos[c * 3 + 0];
    float dy = pos[r * 3 + 1] - pos[c * 3 + 1];
    float dz = pos[r * 3 + 2] - pos[c * 3 + 2];
    g_dist[e] = dx * dx + dy * dy + dz * dz;
}

__global__ void k_embed(const float* __restrict__ x, const float* __restrict__ w,
                        const float* __restrict__ b) {
    int i = blockIdx.x * blockDim.x + threadIdx.x;
    if (i >= NN * HH) return;
    int n = i >> 7, c = i & 127;
    g_h[i] = x[n] * w[c] + b[c];
}

__global__ void k_zero_aggr() {
    int i = blockIdx.x * blockDim.x + threadIdx.x;
    if (i < NN * HH) g_aggr[i] = 0.0f;
}

__global__ void k_zero_pool() {
    int i = blockIdx.x * blockDim.x + threadIdx.x;
    if (i < GG * HH) g_pool[i] = 0.0f;
}

// ---------------------------------------------------------------------------
// Fused edge message MLP + scatter-add (packed f32x2, conflict-free W loads).
__global__ __launch_bounds__(256) void k_edge(
    const int* __restrict__ ei,
    const float* __restrict__ w1, const float* __restrict__ b1,
    const float* __restrict__ w2, const float* __restrict__ b2)
{
    extern __shared__ float sm[];
    float* sA = sm;                      // TE * AS floats
    float* sW = sm + TE * AS;            // KC * HH floats
    int* sCol = (int*)(sW + KC * HH);    // TE ints

    const int tid = threadIdx.x;
    const int warp = tid >> 5, lane = tid & 31;
    const int tx2 = (tid & 15) * 2, ty = tid >> 4;
    const int ebase = blockIdx.x * TE;

    // Gather: each warp fills 8 edge rows (coalesced float4 row loads)
    #pragma unroll
    for (int i = 0; i < 8; i++) {
        int el = warp * 8 + i;
        int e = ebase + el;
        int src = ei[e];        // source j
        int dst = ei[EE + e];   // target i
        float4 vi = *(const float4*)(g_h + (size_t)dst * HH + lane * 4);
        float4 vj = *(const float4*)(g_h + (size_t)src * HH + lane * 4);
        *(float4*)(sA + el * AS + lane * 4) = vi;
        *(float4*)(sA + el * AS + 128 + lane * 4) = vj;
        if (lane == 0) { sA[el * AS + 256] = g_dist[e]; sCol[el] = dst; }
    }

    const float* rA0 = sA + (ty     ) * AS;
    const float* rA1 = sA + (ty + 16) * AS;
    const float* rA2 = sA + (ty + 32) * AS;
    const float* rA3 = sA + (ty + 48) * AS;

    uint64_t acc[4][4];
    init_acc(b1, tx2, acc);

    // GEMM1: K = 256 in chunks of KC, + remainder row 256
    for (int k0 = 0; k0 < 256; k0 += KC) {
        float4 wa = *(const float4*)(w1 + (size_t)k0 * HH + tid * 8);
        float4 wb = *(const float4*)(w1 + (size_t)k0 * HH + tid * 8 + 4);
        __syncthreads();
        *(float4*)(sW + tid * 8) = wa;
        *(float4*)(sW + tid * 8 + 4) = wb;
        __syncthreads();
        #pragma unroll
        for (int kk = 0; kk < KC; kk += 4) {
            float4 a0 = *(const float4*)(rA0 + k0 + kk);
            float4 a1 = *(const float4*)(rA1 + k0 + kk);
            float4 a2 = *(const float4*)(rA2 + k0 + kk);
            float4 a3 = *(const float4*)(rA3 + k0 + kk);
            step_k(a0.x, a1.x, a2.x, a3.x, sW + (kk + 0) * HH, tx2, acc);
            step_k(a0.y, a1.y, a2.y, a3.y, sW + (kk + 1) * HH, tx2, acc);
            step_k(a0.z, a1.z, a2.z, a3.z, sW + (kk + 2) * HH, tx2, acc);
            step_k(a0.w, a1.w, a2.w, a3.w, sW + (kk + 3) * HH, tx2, acc);
        }
    }
    {   // remainder k = 256 (dist column), weights straight from L2
        const float* wr = w1 + (size_t)256 * HH;
        step_k(rA0[256], rA1[256], rA2[256], rA3[256], wr, tx2, acc);
    }
    __syncthreads();

    // silu epilogue -> sA[:, 0:128] at true column positions
    #pragma unroll
    for (int i = 0; i < 4; i++) {
        float* dst = sA + (ty + 16 * i) * AS + tx2;
        #pragma unroll
        for (int p = 0; p < 4; p++) {
            float2 v = unpack2(acc[i][p]);
            v.x = silu_f(v.x);
            v.y = silu_f(v.y);
            *(float2*)(dst + 32 * p) = v;
        }
    }
    init_acc(b2, tx2, acc);
    __syncthreads();

    // GEMM2: K = 128
    for (int k0 = 0; k0 < 128; k0 += KC) {
        float4 wa = *(const float4*)(w2 + (size_t)k0 * HH + tid * 8);
        float4 wb = *(const float4*)(w2 + (size_t)k0 * HH + tid * 8 + 4);
        __syncthreads();
        *(float4*)(sW + tid * 8) = wa;
        *(float4*)(sW + tid * 8 + 4) = wb;
        __syncthreads();
        #pragma unroll
        for (int kk = 0; kk < KC; kk += 4) {
            float4 a0 = *(const float4*)(rA0 + k0 + kk);
            float4 a1 = *(const float4*)(rA1 + k0 + kk);
            float4 a2 = *(const float4*)(rA2 + k0 + kk);
            float4 a3 = *(const float4*)(rA3 + k0 + kk);
            step_k(a0.x, a1.x, a2.x, a3.x, sW + (kk + 0) * HH, tx2, acc);
            step_k(a0.y, a1.y, a2.y, a3.y, sW + (kk + 1) * HH, tx2, acc);
            step_k(a0.z, a1.z, a2.z, a3.z, sW + (kk + 2) * HH, tx2, acc);
            step_k(a0.w, a1.w, a2.w, a3.w, sW + (kk + 3) * HH, tx2, acc);
        }
    }

    // scatter-add into aggr[col]
    #pragma unroll
    for (int i = 0; i < 4; i++) {
        float* base = g_aggr + (size_t)sCol[ty + 16 * i] * HH + tx2;
        #pragma unroll
        for (int p = 0; p < 4; p++) {
            float2 v = unpack2(acc[i][p]);
            atomicAdd(base + 32 * p, v.x);
            atomicAdd(base + 32 * p + 1, v.y);
        }
    }
}

// ---------------------------------------------------------------------------
// Fused node-update MLP (packed f32x2). A = [h | aggr] (64 x 256).
__global__ __launch_bounds__(256) void k_node(
    const float* __restrict__ w1, const float* __restrict__ b1,
    const float* __restrict__ w2, const float* __restrict__ b2)
{
    extern __shared__ float sm[];
    float* sA = sm;
    float* sW = sm + TE * AS;

    const int tid = threadIdx.x;
    const int warp = tid >> 5, lane = tid & 31;
    const int tx2 = (tid & 15) * 2, ty = tid >> 4;
    const int nbase = blockIdx.x * TE;

    #pragma unroll
    for (int i = 0; i < 8; i++) {
        int el = warp * 8 + i;
        int n = nbase + el;
        if (n < NN) {
            float4 vh = *(const float4*)(g_h + (size_t)n * HH + lane * 4);
            float4 va = *(const float4*)(g_aggr + (size_t)n * HH + lane * 4);
            *(float4*)(sA + el * AS + lane * 4) = vh;
            *(float4*)(sA + el * AS + 128 + lane * 4) = va;
        } else {
            float4 z = make_float4(0.f, 0.f, 0.f, 0.f);
            *(float4*)(sA + el * AS + lane * 4) = z;
            *(float4*)(sA + el * AS + 128 + lane * 4) = z;
        }
    }

    const float* rA0 = sA + (ty     ) * AS;
    const float* rA1 = sA + (ty + 16) * AS;
    const float* rA2 = sA + (ty + 32) * AS;
    const float* rA3 = sA + (ty + 48) * AS;

    uint64_t acc[4][4];
    init_acc(b1, tx2, acc);

    // GEMM1: K = 256
    for (int k0 = 0; k0 < 256; k0 += KC) {
        float4 wa = *(const float4*)(w1 + (size_t)k0 * HH + tid * 8);
        float4 wb = *(const float4*)(w1 + (size_t)k0 * HH + tid * 8 + 4);
        __syncthreads();
        *(float4*)(sW + tid * 8) = wa;
        *(float4*)(sW + tid * 8 + 4) = wb;
        __syncthreads();
        #pragma unroll
        for (int kk = 0; kk < KC; kk += 4) {
            float4 a0 = *(const float4*)(rA0 + k0 + kk);
            float4 a1 = *(const float4*)(rA1 + k0 + kk);
            float4 a2 = *(const float4*)(rA2 + k0 + kk);
            float4 a3 = *(const float4*)(rA3 + k0 + kk);
            step_k(a0.x, a1.x, a2.x, a3.x, sW + (kk + 0) * HH, tx2, acc);
            step_k(a0.y, a1.y, a2.y, a3.y, sW + (kk + 1) * HH, tx2, acc);
            step_k(a0.z, a1.z, a2.z, a3.z, sW + (kk + 2) * HH, tx2, acc);
            step_k(a0.w, a1.w, a2.w, a3.w, sW + (kk + 3) * HH, tx2, acc);
        }
    }
    __syncthreads();

    #pragma unroll
    for (int i = 0; i < 4; i++) {
        float* dst = sA + (ty + 16 * i) * AS + tx2;
        #pragma unroll
        for (int p = 0; p < 4; p++) {
            float2 v = unpack2(acc[i][p]);
            v.x = silu_f(v.x);
            v.y = silu_f(v.y);
            *(float2*)(dst + 32 * p) = v;
        }
    }
    init_acc(b2, tx2, acc);
    __syncthreads();

    // GEMM2: K = 128
    for (int k0 = 0; k0 < 128; k0 += KC) {
        float4 wa = *(const float4*)(w2 + (size_t)k0 * HH + tid * 8);
        float4 wb = *(const float4*)(w2 + (size_t)k0 * HH + tid * 8 + 4);
        __syncthreads();
        *(float4*)(sW + tid * 8) = wa;
        *(float4*)(sW + tid * 8 + 4) = wb;
        __syncthreads();
        #pragma unroll
        for (int kk = 0; kk < KC; kk += 4) {
            float4 a0 = *(const float4*)(rA0 + k0 + kk);
            float4 a1 = *(const float4*)(rA1 + k0 + kk);
            float4 a2 = *(const float4*)(rA2 + k0 + kk);
            float4 a3 = *(const float4*)(rA3 + k0 + kk);
            step_k(a0.x, a1.x, a2.x, a3.x, sW + (kk + 0) * HH, tx2, acc);
            step_k(a0.y, a1.y, a2.y, a3.y, sW + (kk + 1) * HH, tx2, acc);
            step_k(a0.z, a1.z, a2.z, a3.z, sW + (kk + 2) * HH, tx2, acc);
            step_k(a0.w, a1.w, a2.w, a3.w, sW + (kk + 3) * HH, tx2, acc);
        }
    }

    #pragma unroll
    for (int i = 0; i < 4; i++) {
        int n = nbase + ty + 16 * i;
        if (n < NN) {
            float* dst = g_h + (size_t)n * HH + tx2;
            #pragma unroll
            for (int p = 0; p < 4; p++) {
                float2 v = unpack2(acc[i][p]);
                *(float2*)(dst + 32 * p) = v;
            }
        }
    }
}

// ---------------------------------------------------------------------------
__global__ void k_pool(const int* __restrict__ batch) {
    int i = blockIdx.x * blockDim.x + threadIdx.x;
    if (i >= NN * 32) return;
    int n = i >> 5, c4 = (i & 31) * 4;
    int b = batch[n];
    const float* hr = g_h + (size_t)n * HH + c4;
    float* pr = g_pool + (size_t)b * HH + c4;
    atomicAdd(pr + 0, hr[0]);
    atomicAdd(pr + 1, hr[1]);
    atomicAdd(pr + 2, hr[2]);
    atomicAdd(pr + 3, hr[3]);
}

__global__ void k_out(const float* __restrict__ w1, const float* __restrict__ b1,
                      const float* __restrict__ w2, const float* __restrict__ b2,
                      float* __restrict__ out) {
    __shared__ float sg[GG * HH];   // 32 KB
    __shared__ float sh[GG * 32];   // 8 KB
    int tid = threadIdx.x;
    for (int i = tid; i < GG * HH; i += 256) sg[i] = g_pool[i];
    __syncthreads();
    for (int p = tid; p < GG * 32; p += 256) {
        int g = p >> 5, j = p & 31;
        float s = b1[j];
        #pragma unroll 4
        for (int k = 0; k < HH; k++) s += sg[g * HH + k] * w1[k * 32 + j];
        sh[p] = silu_f(s);
    }
    __syncthreads();
    if (tid < GG) {
        float s = b2[0];
        #pragma unroll
        for (int j = 0; j < 32; j++) s += sh[tid * 32 + j] * w2[j];
        out[tid] = s;
    }
}

// ---------------------------------------------------------------------------
extern "C" void kernel_launch(void* const* d_in, const int* in_sizes, int n_in,
                              void* d_out, int out_size) {
    const float* x       = (const float*)d_in[0];
    const float* pos     = (const float*)d_in[1];
    const int*   ei      = (const int*)d_in[2];
    const int*   batch   = (const int*)d_in[3];
    const float* emb_w   = (const float*)d_in[4];
    const float* emb_b   = (const float*)d_in[5];
    const float* msg_w1  = (const float*)d_in[6];
    const float* msg_b1  = (const float*)d_in[7];
    const float* msg_w2  = (const float*)d_in[8];
    const float* msg_b2  = (const float*)d_in[9];
    const float* node_w1 = (const float*)d_in[10];
    const float* node_b1 = (const float*)d_in[11];
    const float* node_w2 = (const float*)d_in[12];
    const float* node_b2 = (const float*)d_in[13];
    const float* out_w1  = (const float*)d_in[14];
    const float* out_b1  = (const float*)d_in[15];
    const float* out_w2  = (const float*)d_in[16];
    const float* out_b2  = (const float*)d_in[17];
    float* out = (float*)d_out;

    const int SMEM_EDGE = (TE * AS + KC * HH) * 4 + TE * 4;  // 75008 B
    const int SMEM_NODE = (TE * AS + KC * HH) * 4;           // 74752 B
    cudaFuncSetAttribute(k_edge, cudaFuncAttributeMaxDynamicSharedMemorySize, SMEM_EDGE);
    cudaFuncSetAttribute(k_node, cudaFuncAttributeMaxDynamicSharedMemorySize, SMEM_NODE);

    k_dist<<<(EE + 255) / 256, 256>>>(pos, ei);
    k_embed<<<(NN * HH + 255) / 256, 256>>>(x, emb_w, emb_b);

    for (int l = 0; l < LL; l++) {
        k_zero_aggr<<<(NN * HH + 255) / 256, 256>>>();
        k_edge<<<EE / TE, 256, SMEM_EDGE>>>(
            ei,
            msg_w1 + (size_t)l * (2 * HH + 1) * HH, msg_b1 + (size_t)l * HH,
            msg_w2 + (size_t)l * HH * HH,           msg_b2 + (size_t)l * HH);
        k_node<<<(NN + TE - 1) / TE, 256, SMEM_NODE>>>(
            node_w1 + (size_t)l * 2 * HH * HH, node_b1 + (size_t)l * HH,
            node_w2 + (size_t)l * HH * HH,     node_b2 + (size_t)l * HH);
    }

    k_zero_pool<<<(GG * HH + 255) / 256, 256>>>();
    k_pool<<<(NN * 32 + 255) / 256, 256>>>(batch);
    k_out<<<1, 256>>>(out_w1, out_b1, out_w2, out_b2, out);
}

// round 10
// speedup vs baseline: 1.9708x; 1.2070x over previous
#include <cuda_runtime.h>
#include <cstdint>

// Problem constants (fixed by the dataset)
#define NN 30000
#define EE 600000
#define HH 128
#define GG 64
#define LL 4

#define TILE 64        // rows (edges / nodes) per CTA
#define AS 260         // sA row stride in words (260 % 32 == 4 -> conflict-free frags)
#define KSTAGE 32      // k-rows of W staged per chunk

// Scratch (device globals: allocation-free rule)
__device__ __align__(16) float g_dist[EE];
__device__ __align__(16) float g_h[NN * HH];
__device__ __align__(16) float g_aggr[NN * HH];
__device__ __align__(16) float g_pool[GG * HH];

__device__ __forceinline__ float silu_f(float x) {
    return __fdividef(x, 1.0f + __expf(-x));
}
__device__ __forceinline__ uint32_t f2tf32(float f) {
    uint32_t r; asm("cvt.rna.tf32.f32 %0, %1;" : "=r"(r) : "f"(f)); return r;
}
// 3xTF32 split: hi = tf32(v), lo = tf32(v - hi)
__device__ __forceinline__ void split_tf32(float v, uint32_t& hi, uint32_t& lo) {
    hi = f2tf32(v);
    lo = f2tf32(v - __uint_as_float(hi));
}
__device__ __forceinline__ void mma_tf32(float (&d)[4], const uint32_t (&a)[4],
                                         const uint32_t (&b)[2]) {
    asm volatile(
        "mma.sync.aligned.m16n8k8.row.col.f32.tf32.tf32.f32 "
        "{%0,%1,%2,%3}, {%4,%5,%6,%7}, {%8,%9}, {%0,%1,%2,%3};"
        : "+f"(d[0]), "+f"(d[1]), "+f"(d[2]), "+f"(d[3])
        : "r"(a[0]), "r"(a[1]), "r"(a[2]), "r"(a[3]), "r"(b[0]), "r"(b[1]));
}
__device__ __forceinline__ void red2(float* p, float a, float b) {
    asm volatile("red.global.add.v2.f32 [%0], {%1,%2};" :: "l"(p), "f"(a), "f"(b) : "memory");
}
__device__ __forceinline__ void red4(float* p, float a, float b, float c, float d) {
    asm volatile("red.global.add.v4.f32 [%0], {%1,%2,%3,%4};"
                 :: "l"(p), "f"(a), "f"(b), "f"(c), "f"(d) : "memory");
}

// Stage KSTAGE k-rows of W[k][n] (fp32, no rounding) into sW with XOR swizzle:
// word k*HH + (n ^ ((k&3)<<3)). B-frag loads hit 32 distinct banks.
__device__ __forceinline__ void stage_W(float* sW, const float* __restrict__ w,
                                        int k0, int tid) {
    #pragma unroll
    for (int i = 0; i < 4; i++) {
        int k = (tid >> 5) + 8 * i;          // 0..31
        int n0 = (tid & 31) * 4;
        float4 v = *(const float4*)(w + (size_t)(k0 + k) * HH + n0);
        *(float4*)(sW + k * HH + (n0 ^ ((k & 3) << 3))) = v;
    }
}

// One k8 step, 3xTF32: per (i,j) pair issue ah*bh + ah*bl + al*bh.
__device__ __forceinline__ void mma_k8(const float* sA, const float* sW,
                                       int mbase, int nbase, int kg, int kw,
                                       int gid, int kk, float (&acc)[2][4][4]) {
    uint32_t ah[2][4], al[2][4];
    #pragma unroll
    for (int i = 0; i < 2; i++) {
        const float* ra = sA + (mbase + i * 16 + gid) * AS + kg + kk;
        split_tf32(ra[0],          ah[i][0], al[i][0]);
        split_tf32(ra[8 * AS],     ah[i][1], al[i][1]);
        split_tf32(ra[4],          ah[i][2], al[i][2]);
        split_tf32(ra[8 * AS + 4], ah[i][3], al[i][3]);
    }
    const float* rb = sW + (kw + kk) * HH;
    #pragma unroll
    for (int j = 0; j < 4; j++) {
        int nsw = (nbase + j * 8 + gid) ^ (kk << 3);
        uint32_t bh[2], bl[2];
        split_tf32(rb[nsw],          bh[0], bl[0]);
        split_tf32(rb[4 * HH + nsw], bh[1], bl[1]);
        mma_tf32(acc[0][j], ah[0], bh);
        mma_tf32(acc[0][j], ah[0], bl);
        mma_tf32(acc[0][j], al[0], bh);
        mma_tf32(acc[1][j], ah[1], bh);
        mma_tf32(acc[1][j], ah[1], bl);
        mma_tf32(acc[1][j], al[1], bh);
    }
}

// ---------------------------------------------------------------------------
__global__ void k_dist(const float* __restrict__ pos, const int* __restrict__ ei) {
    int e = blockIdx.x * blockDim.x + threadIdx.x;
    if (e >= EE) return;
    int r = ei[e], c = ei[EE + e];
    float dx = pos[r * 3 + 0] - pos[c * 3 + 0];
    float dy = pos[r * 3 + 1] - pos[c * 3 + 1];
    float dz = pos[r * 3 + 2] - pos[c * 3 + 2];
    g_dist[e] = dx * dx + dy * dy + dz * dz;
}
__global__ void k_embed(const float* __restrict__ x, const float* __restrict__ w,
                        const float* __restrict__ b) {
    int i = blockIdx.x * blockDim.x + threadIdx.x;
    if (i >= NN * HH) return;
    int n = i >> 7, c = i & 127;
    g_h[i] = x[n] * w[c] + b[c];
}
__global__ void k_zero_aggr() {
    int i = blockIdx.x * blockDim.x + threadIdx.x;
    if (i < NN * HH) g_aggr[i] = 0.0f;
}
__global__ void k_zero_pool() {
    int i = blockIdx.x * blockDim.x + threadIdx.x;
    if (i < GG * HH) g_pool[i] = 0.0f;
}

// ---------------------------------------------------------------------------
// Fused edge MLP (3xTF32 mma.sync) + scatter. 64 edges/CTA, 8 warps (2M x 4N).
__global__ __launch_bounds__(256) void k_edge(
    const int* __restrict__ ei,
    const float* __restrict__ w1, const float* __restrict__ b1,
    const float* __restrict__ w2, const float* __restrict__ b2)
{
    extern __shared__ float sm[];
    float* sA = sm;                          // TILE*AS
    float* sW = sm + TILE * AS;              // KSTAGE*HH
    int* sCol = (int*)(sW + KSTAGE * HH);    // 64
    int* sSrc = sCol + TILE;                 // 64
    float* sDist = (float*)(sSrc + TILE);    // 64
    float* sW1r = sDist + TILE;              // 128
    float* sB1 = sW1r + HH;                  // 128
    float* sB2 = sB1 + HH;                   // 128

    const int tid = threadIdx.x, wid = tid >> 5, lane = tid & 31;
    const int kk = lane & 3, gid = lane >> 2;
    const int mbase = (wid & 1) * 32;
    const int nbase = (wid >> 1) * 32;
    const int e0 = blockIdx.x * TILE;

    // gather A = [x_i | x_j] (full fp32), plus edge metadata
    #pragma unroll
    for (int i = 0; i < 8; i++) {
        int m = wid * 8 + i;
        int e = e0 + m;
        int src = ei[e], dst = ei[EE + e];
        if (lane == 0) { sCol[m] = dst; sSrc[m] = src; sDist[m] = g_dist[e]; }
        float4 vi = *(const float4*)(g_h + (size_t)dst * HH + lane * 4);
        float4 vj = *(const float4*)(g_h + (size_t)src * HH + lane * 4);
        *(float4*)(sA + m * AS + lane * 4) = vi;
        *(float4*)(sA + m * AS + 128 + lane * 4) = vj;
    }
    if (tid < HH) {
        sW1r[tid] = w1[(size_t)256 * HH + tid];
        sB1[tid] = b1[tid];
        sB2[tid] = b2[tid];
    }
    __syncthreads();

    float acc[2][4][4];
    #pragma unroll
    for (int j = 0; j < 4; j++) {
        int col = nbase + j * 8 + kk * 2;
        float v0 = sB1[col], v1 = sB1[col + 1];
        acc[0][j][0] = v0; acc[0][j][1] = v1; acc[0][j][2] = v0; acc[0][j][3] = v1;
        acc[1][j][0] = v0; acc[1][j][1] = v1; acc[1][j][2] = v0; acc[1][j][3] = v1;
    }

    // GEMM1: K = 256 (the k=256 dist column is a rank-1 update in epilogue1)
    for (int st = 0; st < 8; st++) {
        int k0 = st * KSTAGE;
        __syncthreads();
        stage_W(sW, w1, k0, tid);
        __syncthreads();
        #pragma unroll
        for (int c = 0; c < 4; c++)
            mma_k8(sA, sW, mbase, nbase, k0 + c * 8, c * 8, gid, kk, acc);
    }
    __syncthreads();

    // epilogue1: + dist*w1[256,:] (bias pre-added) -> silu -> fp32 -> sA[:,0:128]
    #pragma unroll
    for (int i = 0; i < 2; i++) {
        int r0 = mbase + i * 16 + gid, r1 = r0 + 8;
        float d0 = sDist[r0], d1 = sDist[r1];
        #pragma unroll
        for (int j = 0; j < 4; j++) {
            int col = nbase + j * 8 + kk * 2;
            float wr0 = sW1r[col], wr1 = sW1r[col + 1];
            float t0 = silu_f(acc[i][j][0] + d0 * wr0);
            float t1 = silu_f(acc[i][j][1] + d0 * wr1);
            float t2 = silu_f(acc[i][j][2] + d1 * wr0);
            float t3 = silu_f(acc[i][j][3] + d1 * wr1);
            *(float2*)(sA + r0 * AS + col) = make_float2(t0, t1);
            *(float2*)(sA + r1 * AS + col) = make_float2(t2, t3);
            float b0 = sB2[col], b1v = sB2[col + 1];
            acc[i][j][0] = b0; acc[i][j][1] = b1v; acc[i][j][2] = b0; acc[i][j][3] = b1v;
        }
    }

    // GEMM2: K = 128
    for (int st = 0; st < 4; st++) {
        int k0 = st * KSTAGE;
        __syncthreads();
        stage_W(sW, w2, k0, tid);
        __syncthreads();
        #pragma unroll
        for (int c = 0; c < 4; c++)
            mma_k8(sA, sW, mbase, nbase, k0 + c * 8, c * 8, gid, kk, acc);
    }

    // epilogue2: vectorized scatter-add into g_aggr[dst]
    #pragma unroll
    for (int i = 0; i < 2; i++) {
        int r0 = mbase + i * 16 + gid, r1 = r0 + 8;
        float* p0 = g_aggr + (size_t)sCol[r0] * HH;
        float* p1 = g_aggr + (size_t)sCol[r1] * HH;
        #pragma unroll
        for (int j = 0; j < 4; j++) {
            int col = nbase + j * 8 + kk * 2;
            red2(p0 + col, acc[i][j][0], acc[i][j][1]);
            red2(p1 + col, acc[i][j][2], acc[i][j][3]);
        }
    }
}

// ---------------------------------------------------------------------------
// Fused node MLP (3xTF32 mma.sync). A = [h | aggr], 64 nodes/CTA.
__global__ __launch_bounds__(256) void k_node(
    const float* __restrict__ w1, const float* __restrict__ b1,
    const float* __restrict__ w2, const float* __restrict__ b2)
{
    extern __shared__ float sm[];
    float* sA = sm;
    float* sW = sm + TILE * AS;
    float* sB1 = sW + KSTAGE * HH;
    float* sB2 = sB1 + HH;

    const int tid = threadIdx.x, wid = tid >> 5, lane = tid & 31;
    const int kk = lane & 3, gid = lane >> 2;
    const int mbase = (wid & 1) * 32;
    const int nbase = (wid >> 1) * 32;
    const int rbase = blockIdx.x * TILE;

    #pragma unroll
    for (int i = 0; i < 8; i++) {
        int m = wid * 8 + i;
        int n = rbase + m;
        float4 vh = make_float4(0.f, 0.f, 0.f, 0.f), va = vh;
        if (n < NN) {
            vh = *(const float4*)(g_h + (size_t)n * HH + lane * 4);
            va = *(const float4*)(g_aggr + (size_t)n * HH + lane * 4);
        }
        *(float4*)(sA + m * AS + lane * 4) = vh;
        *(float4*)(sA + m * AS + 128 + lane * 4) = va;
    }
    if (tid < HH) { sB1[tid] = b1[tid]; sB2[tid] = b2[tid]; }
    __syncthreads();

    float acc[2][4][4];
    #pragma unroll
    for (int j = 0; j < 4; j++) {
        int col = nbase + j * 8 + kk * 2;
        float v0 = sB1[col], v1 = sB1[col + 1];
        acc[0][j][0] = v0; acc[0][j][1] = v1; acc[0][j][2] = v0; acc[0][j][3] = v1;
        acc[1][j][0] = v0; acc[1][j][1] = v1; acc[1][j][2] = v0; acc[1][j][3] = v1;
    }

    for (int st = 0; st < 8; st++) {
        int k0 = st * KSTAGE;
        __syncthreads();
        stage_W(sW, w1, k0, tid);
        __syncthreads();
        #pragma unroll
        for (int c = 0; c < 4; c++)
            mma_k8(sA, sW, mbase, nbase, k0 + c * 8, c * 8, gid, kk, acc);
    }
    __syncthreads();

    #pragma unroll
    for (int i = 0; i < 2; i++) {
        int r0 = mbase + i * 16 + gid, r1 = r0 + 8;
        #pragma unroll
        for (int j = 0; j < 4; j++) {
            int col = nbase + j * 8 + kk * 2;
            float t0 = silu_f(acc[i][j][0]);
            float t1 = silu_f(acc[i][j][1]);
            float t2 = silu_f(acc[i][j][2]);
            float t3 = silu_f(acc[i][j][3]);
            *(float2*)(sA + r0 * AS + col) = make_float2(t0, t1);
            *(float2*)(sA + r1 * AS + col) = make_float2(t2, t3);
            float b0 = sB2[col], b1v = sB2[col + 1];
            acc[i][j][0] = b0; acc[i][j][1] = b1v; acc[i][j][2] = b0; acc[i][j][3] = b1v;
        }
    }

    for (int st = 0; st < 4; st++) {
        int k0 = st * KSTAGE;
        __syncthreads();
        stage_W(sW, w2, k0, tid);
        __syncthreads();
        #pragma unroll
        for (int c = 0; c < 4; c++)
            mma_k8(sA, sW, mbase, nbase, k0 + c * 8, c * 8, gid, kk, acc);
    }

    #pragma unroll
    for (int i = 0; i < 2; i++) {
        int r0 = mbase + i * 16 + gid, r1 = r0 + 8;
        int n0 = rbase + r0, n1 = rbase + r1;
        #pragma unroll
        for (int j = 0; j < 4; j++) {
            int col = nbase + j * 8 + kk * 2;
            if (n0 < NN)
                *(float2*)(g_h + (size_t)n0 * HH + col) = make_float2(acc[i][j][0], acc[i][j][1]);
            if (n1 < NN)
                *(float2*)(g_h + (size_t)n1 * HH + col) = make_float2(acc[i][j][2], acc[i][j][3]);
        }
    }
}

// ---------------------------------------------------------------------------
__global__ void k_pool(const int* __restrict__ batch) {
    int i = blockIdx.x * blockDim.x + threadIdx.x;
    if (i >= NN * 32) return;
    int n = i >> 5, c4 = (i & 31) * 4;
    int b = batch[n];
    const float* hr = g_h + (size_t)n * HH + c4;
    red4(g_pool + (size_t)b * HH + c4, hr[0], hr[1], hr[2], hr[3]);
}

__global__ void k_out(const float* __restrict__ w1, const float* __restrict__ b1,
                      const float* __restrict__ w2, const float* __restrict__ b2,
                      float* __restrict__ out) {
    __shared__ float sg[GG * HH];
    __shared__ float sh[GG * 32];
    int tid = threadIdx.x;
    for (int i = tid; i < GG * HH; i += 256) sg[i] = g_pool[i];
    __syncthreads();
    for (int p = tid; p < GG * 32; p += 256) {
        int g = p >> 5, j = p & 31;
        float s = b1[j];
        #pragma unroll 4
        for (int k = 0; k < HH; k++) s += sg[g * HH + k] * w1[k * 32 + j];
        sh[p] = silu_f(s);
    }
    __syncthreads();
    if (tid < GG) {
        float s = b2[0];
        #pragma unroll
        for (int j = 0; j < 32; j++) s += sh[tid * 32 + j] * w2[j];
        out[tid] = s;
    }
}

// ---------------------------------------------------------------------------
extern "C" void kernel_launch(void* const* d_in, const int* in_sizes, int n_in,
                              void* d_out, int out_size) {
    const float* x       = (const float*)d_in[0];
    const float* pos     = (const float*)d_in[1];
    const int*   ei      = (const int*)d_in[2];
    const int*   batch   = (const int*)d_in[3];
    const float* emb_w   = (const float*)d_in[4];
    const float* emb_b   = (const float*)d_in[5];
    const float* msg_w1  = (const float*)d_in[6];
    const float* msg_b1  = (const float*)d_in[7];
    const float* msg_w2  = (const float*)d_in[8];
    const float* msg_b2  = (const float*)d_in[9];
    const float* node_w1 = (const float*)d_in[10];
    const float* node_b1 = (const float*)d_in[11];
    const float* node_w2 = (const float*)d_in[12];
    const float* node_b2 = (const float*)d_in[13];
    const float* out_w1  = (const float*)d_in[14];
    const float* out_b1  = (const float*)d_in[15];
    const float* out_w2  = (const float*)d_in[16];
    const float* out_b2  = (const float*)d_in[17];
    float* out = (float*)d_out;

    const int SMEM_EDGE = (TILE * AS + KSTAGE * HH) * 4 + TILE * 3 * 4 + 3 * HH * 4; // 85248
    const int SMEM_NODE = (TILE * AS + KSTAGE * HH) * 4 + 2 * HH * 4;
    cudaFuncSetAttribute(k_edge, cudaFuncAttributeMaxDynamicSharedMemorySize, SMEM_EDGE);
    cudaFuncSetAttribute(k_node, cudaFuncAttributeMaxDynamicSharedMemorySize, SMEM_NODE);

    k_dist<<<(EE + 255) / 256, 256>>>(pos, ei);
    k_embed<<<(NN * HH + 255) / 256, 256>>>(x, emb_w, emb_b);

    const int EGRID = EE / TILE;                 // 9375 (exact)
    const int NGRID = (NN + TILE - 1) / TILE;    // 469

    for (int l = 0; l < LL; l++) {
        k_zero_aggr<<<(NN * HH + 255) / 256, 256>>>();
        k_edge<<<EGRID, 256, SMEM_EDGE>>>(
            ei,
            msg_w1 + (size_t)l * (2 * HH + 1) * HH, msg_b1 + (size_t)l * HH,
            msg_w2 + (size_t)l * HH * HH,           msg_b2 + (size_t)l * HH);
        k_node<<<NGRID, 256, SMEM_NODE>>>(
            node_w1 + (size_t)l * 2 * HH * HH, node_b1 + (size_t)l * HH,
            node_w2 + (size_t)l * HH * HH,     node_b2 + (size_t)l * HH);
    }

    k_zero_pool<<<(GG * HH + 255) / 256, 256>>>();
    k_pool<<<(NN * 32 + 255) / 256, 256>>>(batch);
    k_out<<<1, 256>>>(out_w1, out_b1, out_w2, out_b2, out);
}